// round 3
// baseline (speedup 1.0000x reference)
#include <cuda_runtime.h>

// Problem sizes (fixed by the dataset)
#define BB 8
#define LL 2048
#define DD 128
#define CC 64              // chunks per batch
#define LC (LL / CC)       // 32 events per chunk
#define WPB 4              // warps per block in K2
#define PF 8               // embedding-row prefetch depth in K2
#define EPSC 1e-6f

// Scratch: chunk-local decayed embedding sums and per-chunk partial log-sums.
__device__ float g_T[BB * CC * DD];        // 256 KB
__device__ float g_partial[BB * CC];       // 2 KB

// ---------------------------------------------------------------------------
// K1: T[b,c,:] = sum_{j in chunk} mask_j * e_j * exp(-beta * (t_last - t_j))
// One block per (b,c), 128 threads (thread d owns dim d). Fully parallel.
// ---------------------------------------------------------------------------
__global__ void __launch_bounds__(DD) k1_chunk_sums(
    const int*   __restrict__ ids,
    const float* __restrict__ times,
    const float* __restrict__ mask,
    const float* __restrict__ emb,
    const float* __restrict__ beta_p)
{
    __shared__ float sw[LC];
    __shared__ int   sid[LC];

    const int blk  = blockIdx.x;           // b*CC + c
    const int base = blk * LC;             // == b*LL + c*LC since LL = CC*LC
    const int tid  = threadIdx.x;

    const float beta  = beta_p[0];
    const float tlast = times[base + LC - 1];

    if (tid < LC) {
        float t  = times[base + tid];
        sw[tid]  = mask[base + tid] * expf(-beta * (tlast - t));
        sid[tid] = ids[base + tid];
    }
    __syncthreads();

    float acc = 0.f;
#pragma unroll 8
    for (int k = 0; k < LC; ++k) {
        acc += sw[k] * emb[(size_t)sid[k] * DD + tid];
    }
    g_T[(size_t)blk * DD + tid] = acc;
}

// ---------------------------------------------------------------------------
// K2: per-chunk scan. One warp per (b,c) chunk; lane owns 4 dims (float4).
//   carry = sum_{c'<c} T[b,c'] * exp(-beta*(t0 - t_ref_{c'}))   (t0 = first
//   event time of chunk c; T referenced at last event time of chunk c').
//   Then sequential over the 32 chunk events:
//     S_i = decay_i * A ; lam_i = beta*u_i*(e_i . S_i) ; A = S_i + m_i e_i
//   acc += __logf(lam + eps). Partial written per chunk (deterministic).
// ---------------------------------------------------------------------------
__global__ void __launch_bounds__(32 * WPB) k2_scan(
    const int*   __restrict__ ids,
    const float* __restrict__ times,
    const float* __restrict__ mask,
    const float* __restrict__ emb,
    const float* __restrict__ u_table,
    const float* __restrict__ beta_p)
{
    __shared__ float s_dec[WPB][LC];
    __shared__ float s_bu [WPB][LC];
    __shared__ float s_m  [WPB][LC];
    __shared__ int   s_id [WPB][LC];
    __shared__ float s_cw [WPB][CC];

    const int w    = threadIdx.x >> 5;
    const int lane = threadIdx.x & 31;
    const int g    = blockIdx.x * WPB + w;     // global chunk index = b*CC + c
    const int b    = g / CC;
    const int c    = g % CC;
    const int base = b * LL + c * LC;

    const float beta = beta_p[0];

    // Per-chunk precompute: one event per lane (LC == 32).
    {
        const int k = lane;
        float t  = times[base + k];
        float tp = (k == 0) ? t : times[base + k - 1];
        s_dec[w][k] = expf(-beta * (t - tp));      // 1.0f for k==0
        int id      = ids[base + k];
        s_id[w][k]  = id;
        s_bu[w][k]  = beta * u_table[id];
        s_m [w][k]  = mask[base + k];
    }
    // Carry weights: exp(-beta*(t0 - t_ref(c2))) for c2 < c.
    const float t0 = times[base];
#pragma unroll
    for (int c2 = lane; c2 < CC; c2 += 32) {
        float wgt = 0.f;
        if (c2 < c) {
            float tref = times[b * LL + c2 * LC + LC - 1];
            wgt = expf(-beta * (t0 - tref));
        }
        s_cw[w][c2] = wgt;
    }
    __syncwarp();

    // Carry combine: A = sum_{c2<c} w(c2) * T[b,c2,:]
    float4 A = make_float4(0.f, 0.f, 0.f, 0.f);
    const float4* Tb = (const float4*)g_T + (b * CC) * (DD / 4);
#pragma unroll 4
    for (int c2 = 0; c2 < c; ++c2) {
        float wgt = s_cw[w][c2];
        float4 T = Tb[c2 * (DD / 4) + lane];
        A.x += wgt * T.x; A.y += wgt * T.y; A.z += wgt * T.z; A.w += wgt * T.w;
    }

    // Prefetch first PF embedding rows (lane's float4 slice of each row).
    const float4* embv = (const float4*)emb;
    float4 eq[PF];
#pragma unroll
    for (int p = 0; p < PF; ++p) {
        eq[p] = embv[(size_t)s_id[w][p] * (DD / 4) + lane];
    }

    float acc = 0.f;
#pragma unroll 1
    for (int ii = 0; ii < LC; ii += PF) {
#pragma unroll
        for (int p = 0; p < PF; ++p) {
            const int i = ii + p;
            float4 e = eq[p];
            // prefetch row i+PF (tail wraps to row 0's id; value unused)
            int kn = (i + PF) & (LC - 1);
            eq[p] = embv[(size_t)s_id[w][kn] * (DD / 4) + lane];

            const float d = s_dec[w][i];
            float Sx = d * A.x, Sy = d * A.y, Sz = d * A.z, Sw = d * A.w;
            float pp = e.x * Sx + e.y * Sy + e.z * Sz + e.w * Sw;
            pp += __shfl_xor_sync(0xffffffff, pp, 16);
            pp += __shfl_xor_sync(0xffffffff, pp, 8);
            pp += __shfl_xor_sync(0xffffffff, pp, 4);
            pp += __shfl_xor_sync(0xffffffff, pp, 2);
            pp += __shfl_xor_sync(0xffffffff, pp, 1);
            float lam = s_bu[w][i] * pp;
            acc += __logf(lam + EPSC);
            const float m = s_m[w][i];
            A.x = Sx + m * e.x; A.y = Sy + m * e.y;
            A.z = Sz + m * e.z; A.w = Sw + m * e.w;
        }
    }

    if (lane == 0) g_partial[g] = acc;
}

// ---------------------------------------------------------------------------
// K3: out[b] = sum over the CC=64 chunk partials. Warp per batch; fixed
// reduction order -> bitwise deterministic across graph replays.
// ---------------------------------------------------------------------------
__global__ void __launch_bounds__(BB * 32) k3_reduce(float* __restrict__ out)
{
    const int b    = threadIdx.x >> 5;
    const int lane = threadIdx.x & 31;
    float s = g_partial[b * CC + lane] + g_partial[b * CC + 32 + lane];
    s += __shfl_xor_sync(0xffffffff, s, 16);
    s += __shfl_xor_sync(0xffffffff, s, 8);
    s += __shfl_xor_sync(0xffffffff, s, 4);
    s += __shfl_xor_sync(0xffffffff, s, 2);
    s += __shfl_xor_sync(0xffffffff, s, 1);
    if (lane == 0) out[b] = s;
}

// ---------------------------------------------------------------------------
extern "C" void kernel_launch(void* const* d_in, const int* in_sizes, int n_in,
                              void* d_out, int out_size)
{
    const int*   ids   = (const int*)d_in[0];
    const float* times = (const float*)d_in[1];
    const float* mask  = (const float*)d_in[2];
    const float* emb   = (const float*)d_in[3];
    const float* u_tab = (const float*)d_in[4];
    const float* beta  = (const float*)d_in[5];
    float* out = (float*)d_out;

    k1_chunk_sums<<<BB * CC, DD>>>(ids, times, mask, emb, beta);
    k2_scan<<<(BB * CC) / WPB, 32 * WPB>>>(ids, times, mask, emb, u_tab, beta);
    k3_reduce<<<1, BB * 32>>>(out);
}

// round 4
// speedup vs baseline: 1.1275x; 1.1275x over previous
#include <cuda_runtime.h>

// Problem sizes (fixed by the dataset)
#define BB 8
#define LL 2048
#define DD 128
#define CC 64              // chunks per batch
#define LC (LL / CC)       // 32 events per chunk
#define WPB 4              // warps per block in K2
#define EPSC 1e-6f

// Scratch: chunk-local decayed embedding sums.
__device__ float g_T[BB * CC * DD];        // 256 KB

// ---------------------------------------------------------------------------
// K1: T[b,c,:] = sum_{j in chunk} mask_j * e_j * exp(-beta * (t_last - t_j))
// One block per (b,c), 256 threads: two halves of 16 events each, fully
// unrolled so all 16 LDGs per thread are front-batched (MLP=16).
// Block 0 also zeroes the 8 output floats (graph node order guarantees this
// completes before K2's atomics).
// ---------------------------------------------------------------------------
__global__ void __launch_bounds__(256) k1_chunk_sums(
    const int*   __restrict__ ids,
    const float* __restrict__ times,
    const float* __restrict__ mask,
    const float* __restrict__ emb,
    const float* __restrict__ beta_p,
    float*       __restrict__ out)
{
    __shared__ float sw[LC];
    __shared__ int   sid[LC];
    __shared__ float part[DD];

    const int blk  = blockIdx.x;           // b*CC + c
    const int base = blk * LC;             // == b*LL + c*LC
    const int tid  = threadIdx.x;
    const int half = tid >> 7;             // 0 or 1
    const int d    = tid & (DD - 1);

    if (blk == 0 && tid < BB) out[tid] = 0.f;

    const float beta  = beta_p[0];
    const float tlast = times[base + LC - 1];

    if (tid < LC) {
        float t  = times[base + tid];
        sw[tid]  = mask[base + tid] * __expf(-beta * (tlast - t));
        sid[tid] = ids[base + tid];
    }
    __syncthreads();

    float acc = 0.f;
    const int k0 = half * (LC / 2);
#pragma unroll
    for (int k = 0; k < LC / 2; ++k) {
        const int j = k0 + k;
        acc += sw[j] * emb[(size_t)sid[j] * DD + d];
    }
    if (half == 1) part[d] = acc;
    __syncthreads();
    if (half == 0) g_T[blk * DD + d] = acc + part[d];
}

// ---------------------------------------------------------------------------
// K2: per-chunk scan, one warp per (b,c) chunk; lane owns 4 dims (float4).
// Carry: A = sum_{c2<c} exp(-beta*(t0-tref_c2)) * T[b,c2]  (4 accumulators).
// Scan (critical path = 8-cyc FFMA chain per step only):
//   S = dec_i * A ; pp_lane = e_i . S (lane slice) -> shared ; A = S + m_i e_i
// Deferred reduction: lane i sums row i of the padded pp tile, one log per
// lane (parallel), single 5-shfl warp sum, one atomicAdd per chunk.
// ---------------------------------------------------------------------------
__global__ void __launch_bounds__(32 * WPB) k2_scan(
    const int*   __restrict__ ids,
    const float* __restrict__ times,
    const float* __restrict__ mask,
    const float* __restrict__ emb,
    const float* __restrict__ u_table,
    const float* __restrict__ beta_p,
    float*       __restrict__ out)
{
    __shared__ float s_dec[WPB][LC];
    __shared__ float s_bu [WPB][LC];
    __shared__ float s_m  [WPB][LC];
    __shared__ int   s_id [WPB][LC];
    __shared__ float s_cw [WPB][CC];
    __shared__ float s_pp [WPB][LC][33];   // padded: conflict-free row reads

    const int w    = threadIdx.x >> 5;
    const int lane = threadIdx.x & 31;
    const int g    = blockIdx.x * WPB + w;     // b*CC + c
    const int b    = g / CC;
    const int c    = g % CC;
    const int base = b * LL + c * LC;

    const float beta = beta_p[0];

    // Per-event precompute (one event per lane, LC == 32).
    {
        float t  = times[base + lane];
        float tp = lane ? times[base + lane - 1] : t;
        s_dec[w][lane] = __expf(-beta * (t - tp));   // 1.0f for lane 0
        int id         = ids[base + lane];
        s_id[w][lane]  = id;
        s_bu[w][lane]  = beta * u_table[id];
        s_m [w][lane]  = mask[base + lane];
    }
    // Carry weights (two per lane). exp arg bounded by beta*horizon ~ 25: finite.
    const float t0 = times[base];
    {
        int   c2   = lane;
        float tref = times[b * LL + c2 * LC + LC - 1];
        s_cw[w][c2] = (c2 < c) ? __expf(-beta * (t0 - tref)) : 0.f;
        c2 += 32;
        tref = times[b * LL + c2 * LC + LC - 1];
        s_cw[w][c2] = (c2 < c) ? __expf(-beta * (t0 - tref)) : 0.f;
    }
    __syncwarp();

    // Carry combine with 4 independent accumulators (breaks the FFMA chain,
    // lets LDGs pipeline at issue rate into L2 hits).
    const float4* Tb = (const float4*)g_T + (b * CC) * (DD / 4);
    float4 A0 = {0,0,0,0}, A1 = {0,0,0,0}, A2 = {0,0,0,0}, A3 = {0,0,0,0};
    int c2 = 0;
    for (; c2 + 4 <= c; c2 += 4) {
        float w0 = s_cw[w][c2], w1 = s_cw[w][c2+1], w2 = s_cw[w][c2+2], w3 = s_cw[w][c2+3];
        float4 T0 = Tb[(c2    ) * 32 + lane];
        float4 T1 = Tb[(c2 + 1) * 32 + lane];
        float4 T2 = Tb[(c2 + 2) * 32 + lane];
        float4 T3 = Tb[(c2 + 3) * 32 + lane];
        A0.x += w0*T0.x; A0.y += w0*T0.y; A0.z += w0*T0.z; A0.w += w0*T0.w;
        A1.x += w1*T1.x; A1.y += w1*T1.y; A1.z += w1*T1.z; A1.w += w1*T1.w;
        A2.x += w2*T2.x; A2.y += w2*T2.y; A2.z += w2*T2.z; A2.w += w2*T2.w;
        A3.x += w3*T3.x; A3.y += w3*T3.y; A3.z += w3*T3.z; A3.w += w3*T3.w;
    }
    for (; c2 < c; ++c2) {
        float w0 = s_cw[w][c2];
        float4 T0 = Tb[c2 * 32 + lane];
        A0.x += w0*T0.x; A0.y += w0*T0.y; A0.z += w0*T0.z; A0.w += w0*T0.w;
    }
    float4 A;
    A.x = (A0.x + A1.x) + (A2.x + A3.x);
    A.y = (A0.y + A1.y) + (A2.y + A3.y);
    A.z = (A0.z + A1.z) + (A2.z + A3.z);
    A.w = (A0.w + A1.w) + (A2.w + A3.w);

    // Prefetch all first-half embedding rows; rows are L2-hot from K1.
    const float4* embv = (const float4*)emb;
    float4 eq[LC / 2];
#pragma unroll
    for (int p = 0; p < LC / 2; ++p)
        eq[p] = embv[(size_t)s_id[w][p] * (DD / 4) + lane];

    // First half: consume row p, prefetch row p+16.
#pragma unroll
    for (int p = 0; p < LC / 2; ++p) {
        float4 e = eq[p];
        eq[p] = embv[(size_t)s_id[w][p + LC / 2] * (DD / 4) + lane];
        const float dcy = s_dec[w][p];
        float Sx = dcy * A.x, Sy = dcy * A.y, Sz = dcy * A.z, Sw_ = dcy * A.w;
        float pp = e.x * Sx + e.y * Sy + e.z * Sz + e.w * Sw_;
        s_pp[w][p][lane] = pp;
        const float m = s_m[w][p];
        A.x = Sx + m * e.x; A.y = Sy + m * e.y;
        A.z = Sz + m * e.z; A.w = Sw_ + m * e.w;
    }
    // Second half: no prefetch.
#pragma unroll
    for (int p = 0; p < LC / 2; ++p) {
        const int i = LC / 2 + p;
        float4 e = eq[p];
        const float dcy = s_dec[w][i];
        float Sx = dcy * A.x, Sy = dcy * A.y, Sz = dcy * A.z, Sw_ = dcy * A.w;
        float pp = e.x * Sx + e.y * Sy + e.z * Sz + e.w * Sw_;
        s_pp[w][i][lane] = pp;
        const float m = s_m[w][i];
        A.x = Sx + m * e.x; A.y = Sy + m * e.y;
        A.z = Sz + m * e.z; A.w = Sw_ + m * e.w;
    }
    __syncwarp();

    // Deferred reduction: lane i owns event i. Row read is bank-conflict-free
    // (addr = lane*33 + k -> bank (lane+k)%32, distinct across lanes per k).
    float sum = 0.f;
#pragma unroll
    for (int k = 0; k < LC; ++k) sum += s_pp[w][lane][k];
    float lg = __logf(s_bu[w][lane] * sum + EPSC);

    lg += __shfl_xor_sync(0xffffffff, lg, 16);
    lg += __shfl_xor_sync(0xffffffff, lg, 8);
    lg += __shfl_xor_sync(0xffffffff, lg, 4);
    lg += __shfl_xor_sync(0xffffffff, lg, 2);
    lg += __shfl_xor_sync(0xffffffff, lg, 1);
    if (lane == 0) atomicAdd(&out[b], lg);
}

// ---------------------------------------------------------------------------
extern "C" void kernel_launch(void* const* d_in, const int* in_sizes, int n_in,
                              void* d_out, int out_size)
{
    const int*   ids   = (const int*)d_in[0];
    const float* times = (const float*)d_in[1];
    const float* mask  = (const float*)d_in[2];
    const float* emb   = (const float*)d_in[3];
    const float* u_tab = (const float*)d_in[4];
    const float* beta  = (const float*)d_in[5];
    float* out = (float*)d_out;

    k1_chunk_sums<<<BB * CC, 256>>>(ids, times, mask, emb, beta, out);
    k2_scan<<<(BB * CC) / WPB, 32 * WPB>>>(ids, times, mask, emb, u_tab, beta, out);
}

// round 6
// speedup vs baseline: 1.3087x; 1.1607x over previous
#include <cuda_runtime.h>

// Problem sizes (fixed by the dataset)
#define BB 8
#define LL 2048
#define DD 128
#define CC 64              // chunks per batch
#define LC (LL / CC)       // 32 events per chunk
#define EPSC 1e-6f

// Scratch: chunk-local decayed embedding sums. Zero-initialized at module
// load; K1 fully overwrites rows for every chunk before K2 reads them, and
// rows with carry weight 0 are only ever multiplied by 0.0f (finite), so
// the product is exactly 0.
__device__ float g_T[BB * CC * DD];        // 256 KB

// ---------------------------------------------------------------------------
// K1: T[b,c,:] = sum_{j in chunk} mask_j * e_j * exp(-beta * (t_last - t_j))
// One block per (b,c), 256 threads: two halves of 16 events each, fully
// unrolled so all 16 LDGs per thread are front-batched (MLP=16).
// Block 0 also zeroes the 8 output floats.
// ---------------------------------------------------------------------------
__global__ void __launch_bounds__(256) k1_chunk_sums(
    const int*   __restrict__ ids,
    const float* __restrict__ times,
    const float* __restrict__ mask,
    const float* __restrict__ emb,
    const float* __restrict__ beta_p,
    float*       __restrict__ out)
{
    __shared__ float sw[LC];
    __shared__ int   sid[LC];
    __shared__ float part[DD];

    const int blk  = blockIdx.x;           // b*CC + c
    const int base = blk * LC;             // == b*LL + c*LC
    const int tid  = threadIdx.x;
    const int half = tid >> 7;             // 0 or 1
    const int d    = tid & (DD - 1);

    if (blk == 0 && tid < BB) out[tid] = 0.f;

    const float beta  = beta_p[0];
    const float tlast = times[base + LC - 1];

    if (tid < LC) {
        float t  = times[base + tid];
        sw[tid]  = mask[base + tid] * __expf(-beta * (tlast - t));
        sid[tid] = ids[base + tid];
    }
    __syncthreads();

    float acc = 0.f;
    const int k0 = half * (LC / 2);
#pragma unroll
    for (int k = 0; k < LC / 2; ++k) {
        const int j = k0 + k;
        acc += sw[j] * emb[(size_t)sid[j] * DD + d];
    }
    if (half == 1) part[d] = acc;
    __syncthreads();
    if (half == 0) g_T[blk * DD + d] = acc + part[d];
}

// ---------------------------------------------------------------------------
// K2: one block (128 thr, 4 warps) per chunk; 512 blocks.
//  Phase A (all warps): stage E rows to shared + split carry-combine
//    (16 chunk-sums per warp, fixed-trip fully unrolled, zero weights for
//     c2 >= c) -> partials in shared.
//  Phase B (warp 0): combine carry, 32-step scan with shared-resident E and
//    a 4-deep ring prefetch (no spills), per-lane partial dots to padded
//    shared, then lane-parallel log + 5-shfl sum + one atomicAdd.
// ---------------------------------------------------------------------------
__global__ void __launch_bounds__(128) k2_scan(
    const int*   __restrict__ ids,
    const float* __restrict__ times,
    const float* __restrict__ mask,
    const float* __restrict__ emb,
    const float* __restrict__ u_table,
    const float* __restrict__ beta_p,
    float*       __restrict__ out)
{
    __shared__ float4 s_E4[LC * 32];       // 32 rows x 32 float4 = 16 KB
    __shared__ float4 s_Ap4[4 * 32];       // per-warp carry partials
    __shared__ float  s_pp[LC][33];        // padded: conflict-free row reads
    __shared__ float  s_cw[CC];
    __shared__ float  s_dec[LC], s_bu[LC], s_m[LC];
    __shared__ int    s_id[LC];

    const int tid  = threadIdx.x;
    const int w    = tid >> 5;
    const int lane = tid & 31;
    const int g    = blockIdx.x;           // b*CC + c
    const int b    = g >> 6;
    const int c    = g & (CC - 1);
    const int base = b * LL + c * LC;

    const float beta = beta_p[0];

    if (tid < LC) {
        float t  = times[base + tid];
        float tp = tid ? times[base + tid - 1] : t;
        s_dec[tid] = __expf(-beta * (t - tp));    // 1.0f for tid==0
        int id     = ids[base + tid];
        s_id[tid]  = id;
        s_bu[tid]  = beta * u_table[id];
        s_m [tid]  = mask[base + tid];
    } else if (tid < 32 + CC) {
        int c2 = tid - 32;
        float wgt = 0.f;
        if (c2 < c) {
            float t0   = times[base];
            float tref = times[b * LL + c2 * LC + LC - 1];
            wgt = __expf(-beta * (t0 - tref));
        }
        s_cw[c2] = wgt;
    }
    __syncthreads();

    // --- Phase A1: cooperative E stage (coalesced, MLP=8 per thread) ---
    const float4* embv = (const float4*)emb;
#pragma unroll
    for (int it = 0; it < 8; ++it) {
        int idx = it * 128 + tid;          // idx = row*32 + f4
        int row = idx >> 5, f4 = idx & 31;
        s_E4[idx] = embv[(size_t)s_id[row] * 32 + f4];
    }

    // --- Phase A2: carry partial, 16 chunks per warp, 4 accumulators ---
    const float4* Tb = (const float4*)g_T + (b * CC) * 32;
    float4 A0 = {0,0,0,0}, A1 = {0,0,0,0}, A2 = {0,0,0,0}, A3 = {0,0,0,0};
    const int c2b = w * 16;
#pragma unroll
    for (int k = 0; k < 16; k += 4) {
        float w0 = s_cw[c2b + k],     w1 = s_cw[c2b + k + 1];
        float w2 = s_cw[c2b + k + 2], w3 = s_cw[c2b + k + 3];
        float4 T0 = Tb[(c2b + k    ) * 32 + lane];
        float4 T1 = Tb[(c2b + k + 1) * 32 + lane];
        float4 T2 = Tb[(c2b + k + 2) * 32 + lane];
        float4 T3 = Tb[(c2b + k + 3) * 32 + lane];
        A0.x += w0*T0.x; A0.y += w0*T0.y; A0.z += w0*T0.z; A0.w += w0*T0.w;
        A1.x += w1*T1.x; A1.y += w1*T1.y; A1.z += w1*T1.z; A1.w += w1*T1.w;
        A2.x += w2*T2.x; A2.y += w2*T2.y; A2.z += w2*T2.z; A2.w += w2*T2.w;
        A3.x += w3*T3.x; A3.y += w3*T3.y; A3.z += w3*T3.z; A3.w += w3*T3.w;
    }
    float4 P;
    P.x = (A0.x + A1.x) + (A2.x + A3.x);
    P.y = (A0.y + A1.y) + (A2.y + A3.y);
    P.z = (A0.z + A1.z) + (A2.z + A3.z);
    P.w = (A0.w + A1.w) + (A2.w + A3.w);
    s_Ap4[w * 32 + lane] = P;
    __syncthreads();

    // --- Phase B: warp 0 only ---
    if (w == 0) {
        float4 a0 = s_Ap4[lane], a1 = s_Ap4[32 + lane];
        float4 a2 = s_Ap4[64 + lane], a3 = s_Ap4[96 + lane];
        float4 A;
        A.x = (a0.x + a1.x) + (a2.x + a3.x);
        A.y = (a0.y + a1.y) + (a2.y + a3.y);
        A.z = (a0.z + a1.z) + (a2.z + a3.z);
        A.w = (a0.w + a1.w) + (a2.w + a3.w);

        // 4-deep ring prefetch from shared (16 regs, cannot spill-thrash).
        float4 eq[4];
#pragma unroll
        for (int p = 0; p < 4; ++p) eq[p] = s_E4[p * 32 + lane];

#pragma unroll
        for (int i = 0; i < LC; ++i) {
            float4 e = eq[i & 3];
            int nx = i + 4;
            if (nx < LC) eq[i & 3] = s_E4[nx * 32 + lane];
            const float d = s_dec[i];
            float Sx = d * A.x, Sy = d * A.y, Sz = d * A.z, Sw_ = d * A.w;
            s_pp[i][lane] = e.x * Sx + e.y * Sy + e.z * Sz + e.w * Sw_;
            const float m = s_m[i];
            A.x = Sx + m * e.x; A.y = Sy + m * e.y;
            A.z = Sz + m * e.z; A.w = Sw_ + m * e.w;
        }
        __syncwarp();

        // Lane i owns event i; padded rows -> conflict-free.
        float sum = 0.f;
#pragma unroll
        for (int k = 0; k < LC; ++k) sum += s_pp[lane][k];
        float lg = __logf(s_bu[lane] * sum + EPSC);

        lg += __shfl_xor_sync(0xffffffff, lg, 16);
        lg += __shfl_xor_sync(0xffffffff, lg, 8);
        lg += __shfl_xor_sync(0xffffffff, lg, 4);
        lg += __shfl_xor_sync(0xffffffff, lg, 2);
        lg += __shfl_xor_sync(0xffffffff, lg, 1);
        if (lane == 0) atomicAdd(&out[b], lg);
    }
}

// ---------------------------------------------------------------------------
extern "C" void kernel_launch(void* const* d_in, const int* in_sizes, int n_in,
                              void* d_out, int out_size)
{
    const int*   ids   = (const int*)d_in[0];
    const float* times = (const float*)d_in[1];
    const float* mask  = (const float*)d_in[2];
    const float* emb   = (const float*)d_in[3];
    const float* u_tab = (const float*)d_in[4];
    const float* beta  = (const float*)d_in[5];
    float* out = (float*)d_out;

    k1_chunk_sums<<<BB * CC, 256>>>(ids, times, mask, emb, beta, out);
    k2_scan<<<BB * CC, 128>>>(ids, times, mask, emb, u_tab, beta, out);
}

// round 7
// speedup vs baseline: 1.3359x; 1.0208x over previous
#include <cuda_runtime.h>

// Problem sizes (fixed by the dataset)
#define BB 8
#define LL 2048
#define DD 128
#define CC 64              // chunks per batch
#define LC 32              // events per chunk (LL / CC)
#define EPSC 1e-6f

// Chunk-local decayed embedding sums (referenced at each chunk's last time).
__device__ float    g_T[BB * CC * DD];     // 256 KB
// Monotone grid-barrier ticket counter. Never reset: each launch's 512
// arrivals advance it by 512; target = next multiple of 512. Deterministic
// and safe across graph replays (wraps after ~8M launches).
__device__ unsigned g_cnt = 0;

// ---------------------------------------------------------------------------
// Fused kernel: one block (128 thr) per chunk (b,c); 512 blocks = ONE wave
// (>=8 blocks/SM fit -> all co-resident -> software grid barrier is safe).
//
// Phase 1: stage 32 embedding rows into smem (kept for phase 2), compute
//          T[b,c,:] = sum_j m_j e_j exp(-beta(tlast - t_j)), store to g_T.
// Grid barrier (ticket spin).
// Phase 2: carry A = sum_{c2<c} exp(-beta(t0 - tref_c2)) T[b,c2] (predicated
//          loads, 16 chunks/warp) ; factorized scan with per-chunk anchor t0:
//          lam_i = beta u_i v_i (e_i . (A + sum_{j<i} w_j e_j)),
//          v_i = exp(-beta(t_i-t0)), w_j = m_j exp(+beta(t_j-t0)).
//          All 4 warps scan 8 events each (prior warps' z-sums added first).
//          Deferred per-lane dots -> padded smem -> 4-thread/event reduce ->
//          parallel logs -> warp0 sum -> one atomicAdd per chunk.
// ---------------------------------------------------------------------------
__global__ void __launch_bounds__(128) hawkes_fused(
    const int*   __restrict__ ids,
    const float* __restrict__ times,
    const float* __restrict__ mask,
    const float* __restrict__ emb,
    const float* __restrict__ u_table,
    const float* __restrict__ beta_p,
    float*       __restrict__ out)
{
    __shared__ float4 s_E4[LC * 32];       // 16 KB: 32 rows x 32 float4
    __shared__ float4 s_part[128];         // T partials, then carry partials
    __shared__ float4 s_zsum[128];         // per-warp z sums
    __shared__ float  s_pp[LC][33];        // padded per-lane dot partials
    __shared__ float  s_cw[CC];
    __shared__ float  s_sw[LC], s_w[LC], s_v[LC], s_bu[LC];
    __shared__ int    s_id[LC];
    __shared__ float  s_r[LC];

    const int tid  = threadIdx.x;
    const int w    = tid >> 5;
    const int lane = tid & 31;
    const int g    = blockIdx.x;           // b*CC + c
    const int b    = g >> 6;
    const int c    = g & (CC - 1);
    const int base = b * LL + c * LC;

    const float beta = beta_p[0];

    if (g == 0 && tid < BB) out[tid] = 0.f;

    const float t0    = times[base];
    const float tlast = times[base + LC - 1];

    if (tid < LC) {
        float t  = times[base + tid];
        float m  = mask[base + tid];
        int   id = ids[base + tid];
        s_id[tid] = id;
        s_sw[tid] = m * __expf(beta * (t - tlast));   // T weight (<= m)
        s_w [tid] = m * __expf(beta * (t - t0));      // z weight (bounded by chunk span)
        s_v [tid] = __expf(-beta * (t - t0));         // re-reference factor
        s_bu[tid] = beta * u_table[id];
    } else if (tid < 32 + CC) {
        int c2 = tid - 32;
        float wgt = 0.f;
        if (c2 < c) {
            float tref = times[b * LL + c2 * LC + LC - 1];
            wgt = __expf(-beta * (t0 - tref));
        }
        s_cw[c2] = wgt;
    }
    __syncthreads();

    // --- Phase 1a: cooperative E gather (coalesced 512B rows, MLP=8) ---
    const float4* embv = (const float4*)emb;
#pragma unroll
    for (int it = 0; it < 8; ++it) {
        int idx = it * 128 + tid;          // idx = row*32 + f4
        int row = idx >> 5, f4 = idx & 31;
        s_E4[idx] = embv[(size_t)s_id[row] * 32 + f4];
    }
    __syncthreads();

    // --- Phase 1b: T matvec. Warp w sums its 8 rows; combine; store. ---
    {
        float4 a = {0.f, 0.f, 0.f, 0.f};
#pragma unroll
        for (int k = 0; k < 8; ++k) {
            int j = w * 8 + k;
            float swt = s_sw[j];
            float4 e = s_E4[j * 32 + lane];
            a.x += swt * e.x; a.y += swt * e.y; a.z += swt * e.z; a.w += swt * e.w;
        }
        s_part[w * 32 + lane] = a;
    }
    __syncthreads();
    if (tid < 32) {
        float4 a0 = s_part[tid], a1 = s_part[32 + tid];
        float4 a2 = s_part[64 + tid], a3 = s_part[96 + tid];
        float4 T;
        T.x = (a0.x + a1.x) + (a2.x + a3.x);
        T.y = (a0.y + a1.y) + (a2.y + a3.y);
        T.z = (a0.z + a1.z) + (a2.z + a3.z);
        T.w = (a0.w + a1.w) + (a2.w + a3.w);
        ((float4*)g_T)[g * 32 + tid] = T;
    }
    __syncthreads();

    // --- Grid barrier: release (fence) + ticket arrive + acquire spin ---
    __threadfence();
    if (tid == 0) {
        unsigned t = atomicAdd(&g_cnt, 1u);
        unsigned target = ((t >> 9) + 1u) << 9;     // next multiple of 512
        unsigned cur;
        do {
            asm volatile("ld.global.acquire.gpu.u32 %0, [%1];"
                         : "=r"(cur) : "l"(&g_cnt));
        } while (cur < target);
    }
    __syncthreads();

    // --- Phase 2a: carry partials (16 chunks/warp, predicated loads) + z sums
    const float4* Tb = (const float4*)g_T + (b * CC) * 32;
    {
        float4 A0 = {0,0,0,0}, A1 = {0,0,0,0}, A2 = {0,0,0,0}, A3 = {0,0,0,0};
        const int c2b = w * 16;
#pragma unroll
        for (int k = 0; k < 16; k += 4) {
            float w0 = s_cw[c2b + k],     w1 = s_cw[c2b + k + 1];
            float w2 = s_cw[c2b + k + 2], w3 = s_cw[c2b + k + 3];
            // warp-uniform predicates: zero-weight chunks issue no LDG
            if (w0 != 0.f) { float4 T = Tb[(c2b + k    ) * 32 + lane];
                A0.x += w0*T.x; A0.y += w0*T.y; A0.z += w0*T.z; A0.w += w0*T.w; }
            if (w1 != 0.f) { float4 T = Tb[(c2b + k + 1) * 32 + lane];
                A1.x += w1*T.x; A1.y += w1*T.y; A1.z += w1*T.z; A1.w += w1*T.w; }
            if (w2 != 0.f) { float4 T = Tb[(c2b + k + 2) * 32 + lane];
                A2.x += w2*T.x; A2.y += w2*T.y; A2.z += w2*T.z; A2.w += w2*T.w; }
            if (w3 != 0.f) { float4 T = Tb[(c2b + k + 3) * 32 + lane];
                A3.x += w3*T.x; A3.y += w3*T.y; A3.z += w3*T.z; A3.w += w3*T.w; }
        }
        float4 P;
        P.x = (A0.x + A1.x) + (A2.x + A3.x);
        P.y = (A0.y + A1.y) + (A2.y + A3.y);
        P.z = (A0.z + A1.z) + (A2.z + A3.z);
        P.w = (A0.w + A1.w) + (A2.w + A3.w);
        s_part[w * 32 + lane] = P;         // carry partial (reuse buffer)

        float4 zz = {0.f, 0.f, 0.f, 0.f};
#pragma unroll
        for (int k = 0; k < 8; ++k) {
            int j = w * 8 + k;
            float wz = s_w[j];
            float4 e = s_E4[j * 32 + lane];
            zz.x += wz * e.x; zz.y += wz * e.y; zz.z += wz * e.z; zz.w += wz * e.w;
        }
        s_zsum[w * 32 + lane] = zz;
    }
    __syncthreads();

    // --- Phase 2b: every warp scans its 8 events ---
    {
        float4 c0 = s_part[lane],      c1 = s_part[32 + lane];
        float4 c2_ = s_part[64 + lane], c3 = s_part[96 + lane];
        float4 A;
        A.x = (c0.x + c1.x) + (c2_.x + c3.x);
        A.y = (c0.y + c1.y) + (c2_.y + c3.y);
        A.z = (c0.z + c1.z) + (c2_.z + c3.z);
        A.w = (c0.w + c1.w) + (c2_.w + c3.w);
#pragma unroll
        for (int w2 = 0; w2 < 3; ++w2) {
            if (w2 < w) {
                float4 z = s_zsum[w2 * 32 + lane];
                A.x += z.x; A.y += z.y; A.z += z.z; A.w += z.w;
            }
        }
#pragma unroll
        for (int k = 0; k < 8; ++k) {
            int i = w * 8 + k;
            float4 e = s_E4[i * 32 + lane];
            s_pp[i][lane] = e.x * A.x + e.y * A.y + e.z * A.z + e.w * A.w;
            float wz = s_w[i];
            A.x += wz * e.x; A.y += wz * e.y; A.z += wz * e.z; A.w += wz * e.w;
        }
    }
    __syncthreads();

    // --- Phase 2c: 4 threads per event reduce its 32 lane-partials ---
    {
        int e = tid >> 2, q = tid & 3;
        float s = 0.f;
#pragma unroll
        for (int k = 0; k < 8; ++k) s += s_pp[e][q * 8 + k];   // conflict-free
        s += __shfl_xor_sync(0xffffffffu, s, 1);
        s += __shfl_xor_sync(0xffffffffu, s, 2);
        if (q == 0) {
            float lam = s_bu[e] * s_v[e] * s;
            s_r[e] = __logf(lam + EPSC);
        }
    }
    __syncthreads();

    if (w == 0) {
        float lg = s_r[lane];
        lg += __shfl_xor_sync(0xffffffffu, lg, 16);
        lg += __shfl_xor_sync(0xffffffffu, lg, 8);
        lg += __shfl_xor_sync(0xffffffffu, lg, 4);
        lg += __shfl_xor_sync(0xffffffffu, lg, 2);
        lg += __shfl_xor_sync(0xffffffffu, lg, 1);
        if (lane == 0) atomicAdd(&out[b], lg);
    }
}

// ---------------------------------------------------------------------------
extern "C" void kernel_launch(void* const* d_in, const int* in_sizes, int n_in,
                              void* d_out, int out_size)
{
    const int*   ids   = (const int*)d_in[0];
    const float* times = (const float*)d_in[1];
    const float* mask  = (const float*)d_in[2];
    const float* emb   = (const float*)d_in[3];
    const float* u_tab = (const float*)d_in[4];
    const float* beta  = (const float*)d_in[5];
    float* out = (float*)d_out;

    hawkes_fused<<<BB * CC, 128>>>(ids, times, mask, emb, u_tab, beta, out);
}

// round 8
// speedup vs baseline: 1.5044x; 1.1261x over previous
#include <cuda_runtime.h>

// Problem sizes (fixed by the dataset)
#define BB 8
#define LL 2048
#define DD 128
#define CC 64              // chunks per batch
#define LC 32              // events per chunk (LL / CC)
#define EPSC 1e-6f

// Chunk-local decayed embedding sums (referenced at each chunk's last time).
__device__ float    g_T[BB * CC * DD];     // 256 KB
// Per-batch monotone barrier tickets. Never reset: each launch adds 64 per
// batch; target = next multiple of 64 after this block's ticket. Replay-safe.
__device__ unsigned g_cnt[BB];

// ---------------------------------------------------------------------------
// Fused kernel: one block (128 thr) per chunk (b,c); 512 blocks = ONE wave
// (4 blocks/SM resident by smem -> all co-resident -> barrier deadlock-free).
//
// Phase 1: E-gather starts at instruction 0 (broadcast id loads -> LDG.128
//          into registers), overlapped with time/mask/u precompute. Then
//          T[b,c,:] = sum_j m_j e_j exp(-beta(tlast-t_j)) -> g_T.
// Per-BATCH ticket barrier (64 blocks), nanosleep-backoff spin.
// Phase 2: carry A = sum_{c2<c} cw(c2) T[b,c2] (predicated, 16 chunks/warp);
//          factorized in-chunk scan, all 4 warps x 8 events; deferred dots,
//          parallel logs, one atomicAdd per chunk.
// ---------------------------------------------------------------------------
__global__ void __launch_bounds__(128) hawkes_fused(
    const int*   __restrict__ ids,
    const float* __restrict__ times,
    const float* __restrict__ mask,
    const float* __restrict__ emb,
    const float* __restrict__ u_table,
    const float* __restrict__ beta_p,
    float*       __restrict__ out)
{
    __shared__ float4 s_E4[LC * 32];       // 16 KB: 32 rows x 32 float4
    __shared__ float4 s_part[128];         // T partials, then carry partials
    __shared__ float4 s_zsum[128];         // per-warp z sums
    __shared__ float  s_pp[LC][33];        // padded per-lane dot partials
    __shared__ float  s_cw[CC];
    __shared__ float  s_sw[LC], s_w[LC], s_v[LC], s_bu[LC];
    __shared__ float  s_r[LC];

    const int tid  = threadIdx.x;
    const int w    = tid >> 5;
    const int lane = tid & 31;
    const int g    = blockIdx.x;           // b*CC + c
    const int b    = g >> 6;
    const int c    = g & (CC - 1);
    const int base = b * LL + c * LC;

    // ---- Issue the E-gather IMMEDIATELY (no smem dependency, no sync). ----
    // Threads in groups of 32 share a row: the id load is a warp broadcast
    // (first touch DRAM, rest L1-hit); the row load is a coalesced LDG.128.
    const float4* embv = (const float4*)emb;
    float4 ebuf[8];
#pragma unroll
    for (int it = 0; it < 8; ++it) {
        int idx = it * 128 + tid;          // idx = row*32 + f4
        int row = idx >> 5, f4 = idx & 31;
        int id  = __ldg(&ids[base + row]);
        ebuf[it] = embv[(size_t)id * 32 + f4];
    }

    // ---- Overlapped precompute (independent of the gather). ----
    const float beta  = beta_p[0];
    const float t0    = times[base];
    const float tlast = times[base + LC - 1];

    if (c == 0 && tid < BB && tid == 0) out[b] = 0.f;   // batch b's zero

    if (tid < LC) {
        float t  = times[base + tid];
        float m  = mask[base + tid];
        int   id = ids[base + tid];
        s_sw[tid] = m * __expf(beta * (t - tlast));   // T weight (<= m)
        s_w [tid] = m * __expf(beta * (t - t0));      // z weight (chunk-span bounded)
        s_v [tid] = __expf(-beta * (t - t0));         // re-reference factor
        s_bu[tid] = beta * u_table[id];
    } else if (tid < 32 + CC) {
        int c2 = tid - 32;
        float wgt = 0.f;
        if (c2 < c) {
            float tref = times[b * LL + c2 * LC + LC - 1];
            wgt = __expf(-beta * (t0 - tref));
        }
        s_cw[c2] = wgt;
    }

    // Commit gathered rows to smem.
#pragma unroll
    for (int it = 0; it < 8; ++it) s_E4[it * 128 + tid] = ebuf[it];
    __syncthreads();

    // --- Phase 1b: T matvec. Warp w sums its 8 rows; combine; store. ---
    {
        float4 a = {0.f, 0.f, 0.f, 0.f};
#pragma unroll
        for (int k = 0; k < 8; ++k) {
            int j = w * 8 + k;
            float swt = s_sw[j];
            float4 e = s_E4[j * 32 + lane];
            a.x += swt * e.x; a.y += swt * e.y; a.z += swt * e.z; a.w += swt * e.w;
        }
        s_part[w * 32 + lane] = a;
    }
    __syncthreads();
    if (tid < 32) {
        float4 a0 = s_part[tid], a1 = s_part[32 + tid];
        float4 a2 = s_part[64 + tid], a3 = s_part[96 + tid];
        float4 T;
        T.x = (a0.x + a1.x) + (a2.x + a3.x);
        T.y = (a0.y + a1.y) + (a2.y + a3.y);
        T.z = (a0.z + a1.z) + (a2.z + a3.z);
        T.w = (a0.w + a1.w) + (a2.w + a3.w);
        ((float4*)g_T)[g * 32 + tid] = T;
    }
    __syncthreads();

    // --- Per-batch barrier: fence (release) + ticket + backoff spin ---
    __threadfence();
    if (tid == 0) {
        unsigned t = atomicAdd(&g_cnt[b], 1u);
        unsigned target = ((t >> 6) + 1u) << 6;     // next multiple of 64
        unsigned cur;
        for (;;) {
            asm volatile("ld.global.acquire.gpu.u32 %0, [%1];"
                         : "=r"(cur) : "l"(&g_cnt[b]));
            if (cur >= target) break;
            __nanosleep(64);
        }
    }
    __syncthreads();

    // --- Phase 2a: carry partials (16 chunks/warp, predicated loads) + z sums
    const float4* Tb = (const float4*)g_T + (b * CC) * 32;
    {
        float4 A0 = {0,0,0,0}, A1 = {0,0,0,0}, A2 = {0,0,0,0}, A3 = {0,0,0,0};
        const int c2b = w * 16;
#pragma unroll
        for (int k = 0; k < 16; k += 4) {
            float w0 = s_cw[c2b + k],     w1 = s_cw[c2b + k + 1];
            float w2 = s_cw[c2b + k + 2], w3 = s_cw[c2b + k + 3];
            if (w0 != 0.f) { float4 T = Tb[(c2b + k    ) * 32 + lane];
                A0.x += w0*T.x; A0.y += w0*T.y; A0.z += w0*T.z; A0.w += w0*T.w; }
            if (w1 != 0.f) { float4 T = Tb[(c2b + k + 1) * 32 + lane];
                A1.x += w1*T.x; A1.y += w1*T.y; A1.z += w1*T.z; A1.w += w1*T.w; }
            if (w2 != 0.f) { float4 T = Tb[(c2b + k + 2) * 32 + lane];
                A2.x += w2*T.x; A2.y += w2*T.y; A2.z += w2*T.z; A2.w += w2*T.w; }
            if (w3 != 0.f) { float4 T = Tb[(c2b + k + 3) * 32 + lane];
                A3.x += w3*T.x; A3.y += w3*T.y; A3.z += w3*T.z; A3.w += w3*T.w; }
        }
        float4 P;
        P.x = (A0.x + A1.x) + (A2.x + A3.x);
        P.y = (A0.y + A1.y) + (A2.y + A3.y);
        P.z = (A0.z + A1.z) + (A2.z + A3.z);
        P.w = (A0.w + A1.w) + (A2.w + A3.w);
        s_part[w * 32 + lane] = P;         // carry partial (reuse buffer)

        float4 zz = {0.f, 0.f, 0.f, 0.f};
#pragma unroll
        for (int k = 0; k < 8; ++k) {
            int j = w * 8 + k;
            float wz = s_w[j];
            float4 e = s_E4[j * 32 + lane];
            zz.x += wz * e.x; zz.y += wz * e.y; zz.z += wz * e.z; zz.w += wz * e.w;
        }
        s_zsum[w * 32 + lane] = zz;
    }
    __syncthreads();

    // --- Phase 2b: every warp scans its 8 events ---
    {
        float4 c0 = s_part[lane],       c1 = s_part[32 + lane];
        float4 c2_ = s_part[64 + lane], c3 = s_part[96 + lane];
        float4 A;
        A.x = (c0.x + c1.x) + (c2_.x + c3.x);
        A.y = (c0.y + c1.y) + (c2_.y + c3.y);
        A.z = (c0.z + c1.z) + (c2_.z + c3.z);
        A.w = (c0.w + c1.w) + (c2_.w + c3.w);
#pragma unroll
        for (int w2 = 0; w2 < 3; ++w2) {
            if (w2 < w) {
                float4 z = s_zsum[w2 * 32 + lane];
                A.x += z.x; A.y += z.y; A.z += z.z; A.w += z.w;
            }
        }
#pragma unroll
        for (int k = 0; k < 8; ++k) {
            int i = w * 8 + k;
            float4 e = s_E4[i * 32 + lane];
            s_pp[i][lane] = e.x * A.x + e.y * A.y + e.z * A.z + e.w * A.w;
            float wz = s_w[i];
            A.x += wz * e.x; A.y += wz * e.y; A.z += wz * e.z; A.w += wz * e.w;
        }
    }
    __syncthreads();

    // --- Phase 2c: 4 threads per event reduce its 32 lane-partials ---
    {
        int e = tid >> 2, q = tid & 3;
        float s = 0.f;
#pragma unroll
        for (int k = 0; k < 8; ++k) s += s_pp[e][q * 8 + k];   // conflict-free
        s += __shfl_xor_sync(0xffffffffu, s, 1);
        s += __shfl_xor_sync(0xffffffffu, s, 2);
        if (q == 0) {
            float lam = s_bu[e] * s_v[e] * s;
            s_r[e] = __logf(lam + EPSC);
        }
    }
    __syncthreads();

    if (w == 0) {
        float lg = s_r[lane];
        lg += __shfl_xor_sync(0xffffffffu, lg, 16);
        lg += __shfl_xor_sync(0xffffffffu, lg, 8);
        lg += __shfl_xor_sync(0xffffffffu, lg, 4);
        lg += __shfl_xor_sync(0xffffffffu, lg, 2);
        lg += __shfl_xor_sync(0xffffffffu, lg, 1);
        if (lane == 0) atomicAdd(&out[b], lg);
    }
}

// ---------------------------------------------------------------------------
extern "C" void kernel_launch(void* const* d_in, const int* in_sizes, int n_in,
                              void* d_out, int out_size)
{
    const int*   ids   = (const int*)d_in[0];
    const float* times = (const float*)d_in[1];
    const float* mask  = (const float*)d_in[2];
    const float* emb   = (const float*)d_in[3];
    const float* u_tab = (const float*)d_in[4];
    const float* beta  = (const float*)d_in[5];
    float* out = (float*)d_out;

    hawkes_fused<<<BB * CC, 128>>>(ids, times, mask, emb, u_tab, beta, out);
}

// round 10
// speedup vs baseline: 1.5545x; 1.0333x over previous
#include <cuda_runtime.h>

// Problem sizes (fixed by the dataset)
#define BB 8
#define LL 2048
#define DD 128
#define CC 64              // chunks per batch
#define LC 32              // events per chunk (LL / CC)
#define EPSC 1e-6f

// Chunk-local decayed embedding sums (referenced at each chunk's last time).
__device__ float    g_T[BB * CC * DD];     // 256 KB
// Per-batch monotone barrier tickets, PADDED to one 128B line each so spin
// loads for one batch never queue behind arrivals of another. Never reset:
// each launch adds 64 per batch; target = next multiple of 64. Replay-safe.
__device__ unsigned g_cnt[BB * 32];

// ---------------------------------------------------------------------------
// Fused kernel, arrive-early/wait-late: one block (128 thr) per chunk (b,c).
//
//  1. Front-loaded E gather (broadcast id -> LDG.128) overlapped with
//     time/mask/u precompute.
//  2. T[b,c,:] = sum_j m_j e_j exp(-beta(tlast-t_j)) -> g_T; fence; ARRIVE
//     (non-blocking ticket) on the per-batch barrier.
//  3. In-chunk compute while others arrive: per-warp z-sums, factorized scan
//     pp_in[i][lane] = e_i . (sum_{j<i} w_j e_j)   (A excluded; it is
//     chunk-constant and linear, folded in later).
//  4. WAIT (tid0 spin + syncthreads).
//  5. Carry A = sum_{c2<c} cw(c2) T[b,c2] (predicated, 16 chunks/warp);
//     fold e_i . A into pp; 4-thread/event reduce; parallel logs; one
//     atomicAdd per chunk.
// ---------------------------------------------------------------------------
__global__ void __launch_bounds__(128) hawkes_fused(
    const int*   __restrict__ ids,
    const float* __restrict__ times,
    const float* __restrict__ mask,
    const float* __restrict__ emb,
    const float* __restrict__ u_table,
    const float* __restrict__ beta_p,
    float*       __restrict__ out)
{
    __shared__ float4 s_E4[LC * 32];       // 16 KB: 32 rows x 32 float4
    __shared__ float4 s_part[128];         // T partials, then carry partials
    __shared__ float4 s_zsum[128];         // per-warp z sums
    __shared__ float  s_pp[LC][33];        // padded per-lane dot partials
    __shared__ float  s_cw[CC];
    __shared__ float  s_sw[LC], s_w[LC], s_v[LC], s_bu[LC];
    __shared__ float  s_r[LC];

    const int tid  = threadIdx.x;
    const int w    = tid >> 5;
    const int lane = tid & 31;
    const int g    = blockIdx.x;           // b*CC + c
    const int b    = g >> 6;
    const int c    = g & (CC - 1);
    const int base = b * LL + c * LC;

    // ---- 1. E gather at instruction 0 (id broadcast -> coalesced LDG.128) --
    const float4* embv = (const float4*)emb;
    float4 ebuf[8];
#pragma unroll
    for (int it = 0; it < 8; ++it) {
        int idx = it * 128 + tid;          // idx = row*32 + f4
        int row = idx >> 5, f4 = idx & 31;
        int id  = __ldg(&ids[base + row]);
        ebuf[it] = embv[(size_t)id * 32 + f4];
    }

    // ---- Overlapped precompute (independent of the gather). ----
    const float beta  = beta_p[0];
    const float t0    = times[base];
    const float tlast = times[base + LC - 1];

    if (c == 0 && tid == 0) out[b] = 0.f;  // fenced before arrive below

    if (tid < LC) {
        float t  = times[base + tid];
        float m  = mask[base + tid];
        int   id = ids[base + tid];
        s_sw[tid] = m * __expf(beta * (t - tlast));   // T weight (<= m)
        s_w [tid] = m * __expf(beta * (t - t0));      // z weight (chunk-span bounded)
        s_v [tid] = __expf(-beta * (t - t0));         // re-reference factor
        s_bu[tid] = beta * u_table[id];
    } else if (tid < 32 + CC) {
        int c2 = tid - 32;
        float wgt = 0.f;
        if (c2 < c) {
            float tref = times[b * LL + c2 * LC + LC - 1];
            wgt = __expf(-beta * (t0 - tref));
        }
        s_cw[c2] = wgt;
    }

#pragma unroll
    for (int it = 0; it < 8; ++it) s_E4[it * 128 + tid] = ebuf[it];
    __syncthreads();

    // ---- 2. T matvec -> g_T, fence, ARRIVE (non-blocking) ----
    {
        float4 a = {0.f, 0.f, 0.f, 0.f};
#pragma unroll
        for (int k = 0; k < 8; ++k) {
            int j = w * 8 + k;
            float swt = s_sw[j];
            float4 e = s_E4[j * 32 + lane];
            a.x += swt * e.x; a.y += swt * e.y; a.z += swt * e.z; a.w += swt * e.w;
        }
        s_part[w * 32 + lane] = a;
    }
    __syncthreads();
    if (tid < 32) {
        float4 a0 = s_part[tid], a1 = s_part[32 + tid];
        float4 a2 = s_part[64 + tid], a3 = s_part[96 + tid];
        float4 T;
        T.x = (a0.x + a1.x) + (a2.x + a3.x);
        T.y = (a0.y + a1.y) + (a2.y + a3.y);
        T.z = (a0.z + a1.z) + (a2.z + a3.z);
        T.w = (a0.w + a1.w) + (a2.w + a3.w);
        ((float4*)g_T)[g * 32 + tid] = T;
    }
    __syncthreads();
    __threadfence();                        // release g_T (and out[b]=0)
    unsigned target = 0;
    if (tid == 0) {
        unsigned t = atomicAdd(&g_cnt[b * 32], 1u);
        target = ((t >> 6) + 1u) << 6;      // next multiple of 64
    }

    // ---- 3. In-chunk compute while other blocks arrive ----
    {
        float4 zz = {0.f, 0.f, 0.f, 0.f};
#pragma unroll
        for (int k = 0; k < 8; ++k) {
            int j = w * 8 + k;
            float wz = s_w[j];
            float4 e = s_E4[j * 32 + lane];
            zz.x += wz * e.x; zz.y += wz * e.y; zz.z += wz * e.z; zz.w += wz * e.w;
        }
        s_zsum[w * 32 + lane] = zz;
    }
    __syncthreads();
    {
        // In-chunk running sum H (A excluded): prior warps' z-sums + own scan.
        float4 H = {0.f, 0.f, 0.f, 0.f};
#pragma unroll
        for (int w2 = 0; w2 < 3; ++w2) {
            if (w2 < w) {
                float4 z = s_zsum[w2 * 32 + lane];
                H.x += z.x; H.y += z.y; H.z += z.z; H.w += z.w;
            }
        }
#pragma unroll
        for (int k = 0; k < 8; ++k) {
            int i = w * 8 + k;
            float4 e = s_E4[i * 32 + lane];
            s_pp[i][lane] = e.x * H.x + e.y * H.y + e.z * H.z + e.w * H.w;
            float wz = s_w[i];
            H.x += wz * e.x; H.y += wz * e.y; H.z += wz * e.z; H.w += wz * e.w;
        }
    }

    // ---- 4. WAIT (spin overlapped work is done) ----
    if (tid == 0) {
        unsigned cur;
        for (;;) {
            asm volatile("ld.global.acquire.gpu.u32 %0, [%1];"
                         : "=r"(cur) : "l"(&g_cnt[b * 32]));
            if (cur >= target) break;
            __nanosleep(64);
        }
    }
    __syncthreads();

    // ---- 5a. Carry partials (16 chunks/warp, predicated loads) ----
    const float4* Tb = (const float4*)g_T + (b * CC) * 32;
    {
        float4 A0 = {0,0,0,0}, A1 = {0,0,0,0}, A2 = {0,0,0,0}, A3 = {0,0,0,0};
        const int c2b = w * 16;
#pragma unroll
        for (int k = 0; k < 16; k += 4) {
            float w0 = s_cw[c2b + k],     w1 = s_cw[c2b + k + 1];
            float w2 = s_cw[c2b + k + 2], w3 = s_cw[c2b + k + 3];
            if (w0 != 0.f) { float4 T = Tb[(c2b + k    ) * 32 + lane];
                A0.x += w0*T.x; A0.y += w0*T.y; A0.z += w0*T.z; A0.w += w0*T.w; }
            if (w1 != 0.f) { float4 T = Tb[(c2b + k + 1) * 32 + lane];
                A1.x += w1*T.x; A1.y += w1*T.y; A1.z += w1*T.z; A1.w += w1*T.w; }
            if (w2 != 0.f) { float4 T = Tb[(c2b + k + 2) * 32 + lane];
                A2.x += w2*T.x; A2.y += w2*T.y; A2.z += w2*T.z; A2.w += w2*T.w; }
            if (w3 != 0.f) { float4 T = Tb[(c2b + k + 3) * 32 + lane];
                A3.x += w3*T.x; A3.y += w3*T.y; A3.z += w3*T.z; A3.w += w3*T.w; }
        }
        float4 P;
        P.x = (A0.x + A1.x) + (A2.x + A3.x);
        P.y = (A0.y + A1.y) + (A2.y + A3.y);
        P.z = (A0.z + A1.z) + (A2.z + A3.z);
        P.w = (A0.w + A1.w) + (A2.w + A3.w);
        s_part[w * 32 + lane] = P;
    }
    __syncthreads();

    // ---- 5b. Fold e_i . A into pp (A is chunk-constant) ----
    {
        float4 p0 = s_part[lane],      p1 = s_part[32 + lane];
        float4 p2 = s_part[64 + lane], p3 = s_part[96 + lane];
        float4 A;
        A.x = (p0.x + p1.x) + (p2.x + p3.x);
        A.y = (p0.y + p1.y) + (p2.y + p3.y);
        A.z = (p0.z + p1.z) + (p2.z + p3.z);
        A.w = (p0.w + p1.w) + (p2.w + p3.w);
#pragma unroll
        for (int k = 0; k < 8; ++k) {
            int i = w * 8 + k;
            float4 e = s_E4[i * 32 + lane];
            s_pp[i][lane] += e.x * A.x + e.y * A.y + e.z * A.z + e.w * A.w;
        }
    }
    __syncthreads();

    // ---- 5c. 4 threads per event reduce its 32 lane-partials ----
    {
        int e = tid >> 2, q = tid & 3;
        float s = 0.f;
#pragma unroll
        for (int k = 0; k < 8; ++k) s += s_pp[e][q * 8 + k];   // conflict-free
        s += __shfl_xor_sync(0xffffffffu, s, 1);
        s += __shfl_xor_sync(0xffffffffu, s, 2);
        if (q == 0) {
            float lam = s_bu[e] * s_v[e] * s;
            s_r[e] = __logf(lam + EPSC);
        }
    }
    __syncthreads();

    if (w == 0) {
        float lg = s_r[lane];
        lg += __shfl_xor_sync(0xffffffffu, lg, 16);
        lg += __shfl_xor_sync(0xffffffffu, lg, 8);
        lg += __shfl_xor_sync(0xffffffffu, lg, 4);
        lg += __shfl_xor_sync(0xffffffffu, lg, 2);
        lg += __shfl_xor_sync(0xffffffffu, lg, 1);
        if (lane == 0) atomicAdd(&out[b], lg);
    }
}

// ---------------------------------------------------------------------------
extern "C" void kernel_launch(void* const* d_in, const int* in_sizes, int n_in,
                              void* d_out, int out_size)
{
    const int*   ids   = (const int*)d_in[0];
    const float* times = (const float*)d_in[1];
    const float* mask  = (const float*)d_in[2];
    const float* emb   = (const float*)d_in[3];
    const float* u_tab = (const float*)d_in[4];
    const float* beta  = (const float*)d_in[5];
    float* out = (float*)d_out;

    hawkes_fused<<<BB * CC, 128>>>(ids, times, mask, emb, u_tab, beta, out);
}